// round 13
// baseline (speedup 1.0000x reference)
#include <cuda_runtime.h>
#include <math.h>

constexpr int H_   = 768;
constexpr int NC_  = 8;       // chunks
constexpr int NL_  = 8921;    // labels
constexpr int NN_  = 4;       // notes
constexpr int JB_  = 1115;    // lw bucket width (8921 = 8*1115 + 1)

constexpr int ESEG  = 16;     // segments per encoding chunk
constexpr int EROWS = 32;     // 16*32 = 512 rows/chunk
constexpr int LSEG  = 32;     // segments per lw bucket
constexpr int LROWS = 35;     // 32*35 = 1120 >= 1116
constexpr int HG    = 3;      // 768 / 256 column groups
constexpr int ENC_BLOCKS = NC_ * ESEG * HG;   // 384
constexpr int LW_BLOCKS  = NC_ * LSEG * HG;   // 768
constexpr int GRID       = ENC_BLOCKS + LW_BLOCKS;  // 1152

// Accumulators: zero at module load; the finale re-zeroes exactly what it
// consumed -> invariant "zero on entry" holds across graph replays.
__device__ float g_CS[NC_ * H_];          // per-chunk encoding column sums
__device__ float g_L [NC_ * H_];          // per-bucket lw column sums
__device__ unsigned int g_cnt;            // arrival counter (reset by finale)

__device__ __forceinline__ void redg_add(float* p, float v) {
    asm volatile("red.relaxed.gpu.global.add.f32 [%0], %1;" :: "l"(p), "f"(v) : "memory");
}
__device__ __forceinline__ unsigned int gate_add_acq_rel(unsigned int* p) {
    unsigned int old;
    asm volatile("atom.acq_rel.gpu.global.add.u32 %0, [%1], %2;"
                 : "=r"(old) : "l"(p), "r"(1u) : "memory");
    return old;
}
__device__ __forceinline__ float ldg_gpu(const float* p) {
    float v;
    asm volatile("ld.relaxed.gpu.global.f32 %0, [%1];" : "=f"(v) : "l"(p) : "memory");
    return v;
}
__device__ __forceinline__ void stg_gpu_u32(unsigned int* p, unsigned int v) {
    asm volatile("st.relaxed.gpu.global.u32 [%0], %1;" :: "l"(p), "r"(v) : "memory");
}

__global__ __launch_bounds__(256, 8) void fused_kernel(const float* __restrict__ enc,
                                                       const float* __restrict__ lw,
                                                       const void* __restrict__ idsRaw,
                                                       float* __restrict__ out) {
    const int b   = blockIdx.x;
    const int tid = threadIdx.x;

    // ---------------- Phase 1: streaming block sums + one REDG per thread ----------------
    if (b < ENC_BLOCKS) {
        int c   = b / (ESEG * HG);
        int rem = b % (ESEG * HG);
        int s   = rem / HG;
        int hg  = rem % HG;
        int h   = hg * 256 + tid;
        const float* p = enc + (size_t)(c * 512 + s * EROWS) * H_ + h;
        float a0 = 0.f, a1 = 0.f, a2 = 0.f, a3 = 0.f;
        #pragma unroll
        for (int r = 0; r < EROWS; r += 4) {
            a0 += p[(r + 0) * H_];
            a1 += p[(r + 1) * H_];
            a2 += p[(r + 2) * H_];
            a3 += p[(r + 3) * H_];
        }
        redg_add(&g_CS[c * H_ + h], (a0 + a1) + (a2 + a3));
    } else {
        int bb  = b - ENC_BLOCKS;
        int c   = bb / (LSEG * HG);
        int rem = bb % (LSEG * HG);
        int s   = rem / HG;
        int hg  = rem % HG;
        int h   = hg * 256 + tid;
        int r0   = c * JB_ + s * LROWS;
        int rend = min(r0 + LROWS, (c == NC_ - 1) ? NL_ : (c + 1) * JB_);
        float a0 = 0.f, a1 = 0.f, a2 = 0.f, a3 = 0.f;
        int r = r0;
        for (; r + 4 <= rend; r += 4) {
            a0 += lw[(size_t)(r + 0) * H_ + h];
            a1 += lw[(size_t)(r + 1) * H_ + h];
            a2 += lw[(size_t)(r + 2) * H_ + h];
            a3 += lw[(size_t)(r + 3) * H_ + h];
        }
        float tail = 0.f;
        for (; r < rend; ++r) tail += lw[(size_t)r * H_ + h];
        redg_add(&g_L[c * H_ + h], ((a0 + a1) + (a2 + a3)) + tail);
    }

    // ---------------- Gate: last-arriving block runs the finale ----------------
    __syncthreads();                 // block's REDGs happen-before tid0's release RMW
    __shared__ bool sLast;
    if (tid == 0)
        sLast = (gate_add_acq_rel(&g_cnt) == (unsigned)(GRID - 1));
    __syncthreads();
    if (!sLast) return;
    if (tid == 0) stg_gpu_u32(&g_cnt, 0u);   // reset for next replay (all arrivals done)

    // ---------------- Finale (one block): combine + sigmoid + self-rezero ----------------
    __shared__ float sCS[NC_][256];
    __shared__ float sL [NC_][256];

    // note_end_chunk_ids: detect int64 vs int32 layout
    const int* w = (const int*)idsRaw;
    int ids[NN_];
    {
        bool is64 = true;
        int v[NN_];
        #pragma unroll
        for (int i = 0; i < NN_; ++i) {
            int lo = w[2 * i], hi = w[2 * i + 1];
            v[i] = lo;
            if (hi != 0 || lo < 0 || lo >= NC_) is64 = false;
        }
        #pragma unroll
        for (int i = 0; i + 1 < NN_; ++i)
            if (v[i] > v[i + 1]) is64 = false;
        #pragma unroll
        for (int i = 0; i < NN_; ++i) ids[i] = is64 ? v[i] : w[i];
    }

    for (int g = 0; g < HG; ++g) {
        int h = g * 256 + tid;
        #pragma unroll
        for (int c = 0; c < NC_; ++c) {
            sCS[c][tid] = ldg_gpu(&g_CS[c * H_ + h]);
            sL [c][tid] = ldg_gpu(&g_L [c * H_ + h]);
            g_CS[c * H_ + h] = 0.f;      // rezero consumed slots for next replay
            g_L [c * H_ + h] = 0.f;
        }
        float bnd[NC_ - 1];
        #pragma unroll
        for (int k = 1; k < NC_; ++k)
            bnd[k - 1] = lw[(size_t)(JB_ * k) * H_ + h];

        float Ptot = 0.f;
        #pragma unroll
        for (int c = 0; c < NC_; ++c) Ptot += sCS[c][tid];

        #pragma unroll
        for (int n = 0; n < NN_; ++n) {
            // softmax weight row: masked(n,c) <=> c <= ids[n]; cnt = #{i: ids[i] < c}
            float Wn[NC_];
            #pragma unroll
            for (int c = 0; c < NC_; ++c) {
                int cnt = 0;
                #pragma unroll
                for (int i = 0; i < NN_; ++i) cnt += (ids[i] < c) ? 1 : 0;
                bool un = (ids[n] < c);
                Wn[c] = (cnt > 0) ? (un ? 1.0f / (float)cnt : 0.0f) : 0.25f;
            }

            float dot = 0.f;
            #pragma unroll
            for (int c = 0; c < NC_; ++c) dot += Wn[c] * sL[c][tid];
            float score = Ptot * dot;

            // boundary corrections: j = 1115k straddles chunks (k-1, k) at prefix P[512k]
            float P = 0.f;
            #pragma unroll
            for (int k = 1; k < NC_; ++k) {
                P += sCS[k - 1][tid];
                float wd = Wn[k - 1] - Wn[k];
                score += wd * bnd[k - 1] * P;
            }
            out[n * H_ + h] = 1.0f / (1.0f + expf(-score));
        }
    }
}

extern "C" void kernel_launch(void* const* d_in, const int* in_sizes, int n_in,
                              void* d_out, int out_size) {
    const float* enc = (const float*)d_in[0];   // encoding (4096, 768)
    // d_in[1] = label_queries: provably unused (softmax over the note axis cancels scores)
    const float* lw  = (const float*)d_in[2];   // label_weights flat (768*8921)
    const void*  ids = d_in[3];                 // note_end_chunk_ids (4, int32 or int64)
    float* out = (float*)d_out;                 // (4, 768) float32

    fused_kernel<<<GRID, 256>>>(enc, lw, ids, out);
}

// round 15
// speedup vs baseline: 1.4725x; 1.4725x over previous
#include <cuda_runtime.h>
#include <math.h>

constexpr int H_   = 768;
constexpr int NC_  = 8;       // chunks
constexpr int NL_  = 8921;    // labels
constexpr int NN_  = 4;       // notes
constexpr int JB_  = 1115;    // lw bucket width (8921 = 8*1115 + 1)

constexpr int ESEG  = 16;     // segments per encoding chunk
constexpr int EROWS = 32;     // 16*32 = 512 rows/chunk
constexpr int LSEG  = 32;     // segments per lw bucket
constexpr int LROWS = 35;     // 32*35 = 1120 >= 1116
constexpr int HG    = 3;      // 768 / 256 column groups
constexpr int ENC_BLOCKS = NC_ * ESEG * HG;   // 384
constexpr int LW_BLOCKS  = NC_ * LSEG * HG;   // 768
constexpr int GRID       = ENC_BLOCKS + LW_BLOCKS;  // 1152

// Accumulators. Zero at module load; final2_kernel re-zeroes exactly the slots
// it consumed -> invariant "zero on entry to sum_kernel" holds on every graph
// replay. No counters, no gates, no fences.
__device__ float g_CS[NC_ * H_];          // per-chunk encoding column sums
__device__ float g_L [NC_ * H_];          // per-bucket lw column sums

__device__ __forceinline__ void redg_add(float* p, float v) {
    asm volatile("red.relaxed.gpu.global.add.f32 [%0], %1;" :: "l"(p), "f"(v) : "memory");
}
__device__ __forceinline__ float ldg_gpu(const float* p) {
    float v;
    asm volatile("ld.relaxed.gpu.global.f32 %0, [%1];" : "=f"(v) : "l"(p) : "memory");
    return v;
}

// ---------------- Kernel 1: pure streaming block sums + one REDG per thread ----------------
__global__ __launch_bounds__(256, 8) void sum_kernel(const float* __restrict__ enc,
                                                     const float* __restrict__ lw) {
    const int b   = blockIdx.x;
    const int tid = threadIdx.x;

    if (b < ENC_BLOCKS) {
        int c   = b / (ESEG * HG);
        int rem = b % (ESEG * HG);
        int s   = rem / HG;
        int hg  = rem % HG;
        int h   = hg * 256 + tid;
        const float* p = enc + (size_t)(c * 512 + s * EROWS) * H_ + h;
        float a0 = 0.f, a1 = 0.f, a2 = 0.f, a3 = 0.f;
        #pragma unroll
        for (int r = 0; r < EROWS; r += 4) {
            a0 += p[(r + 0) * H_];
            a1 += p[(r + 1) * H_];
            a2 += p[(r + 2) * H_];
            a3 += p[(r + 3) * H_];
        }
        redg_add(&g_CS[c * H_ + h], (a0 + a1) + (a2 + a3));
    } else {
        int bb  = b - ENC_BLOCKS;
        int c   = bb / (LSEG * HG);
        int rem = bb % (LSEG * HG);
        int s   = rem / HG;
        int hg  = rem % HG;
        int h   = hg * 256 + tid;
        int r0   = c * JB_ + s * LROWS;
        int rend = min(r0 + LROWS, (c == NC_ - 1) ? NL_ : (c + 1) * JB_);
        float a0 = 0.f, a1 = 0.f, a2 = 0.f, a3 = 0.f;
        int r = r0;
        for (; r + 4 <= rend; r += 4) {
            a0 += lw[(size_t)(r + 0) * H_ + h];
            a1 += lw[(size_t)(r + 1) * H_ + h];
            a2 += lw[(size_t)(r + 2) * H_ + h];
            a3 += lw[(size_t)(r + 3) * H_ + h];
        }
        float tail = 0.f;
        for (; r < rend; ++r) tail += lw[(size_t)r * H_ + h];
        redg_add(&g_L[c * H_ + h], ((a0 + a1) + (a2 + a3)) + tail);
    }
}

// ---------------- Kernel 2 (PDL): prologue overlaps sum_kernel; wait; combine ----------------
__global__ __launch_bounds__(128) void final2_kernel(const float* __restrict__ lw,
                                                     const void* __restrict__ idsRaw,
                                                     float* __restrict__ out) {
    const int h = blockIdx.x * 128 + threadIdx.x;   // one column per thread, 768 total

    // ---- prologue: everything independent of the accumulators ----
    float bnd[NC_ - 1];
    #pragma unroll
    for (int k = 1; k < NC_; ++k)
        bnd[k - 1] = lw[(size_t)(JB_ * k) * H_ + h];

    // note_end_chunk_ids: detect int64 vs int32 layout
    const int* w = (const int*)idsRaw;
    int ids[NN_];
    {
        bool is64 = true;
        int v[NN_];
        #pragma unroll
        for (int i = 0; i < NN_; ++i) {
            int lo = w[2 * i], hi = w[2 * i + 1];
            v[i] = lo;
            if (hi != 0 || lo < 0 || lo >= NC_) is64 = false;
        }
        #pragma unroll
        for (int i = 0; i + 1 < NN_; ++i)
            if (v[i] > v[i + 1]) is64 = false;
        #pragma unroll
        for (int i = 0; i < NN_; ++i) ids[i] = is64 ? v[i] : w[i];
    }

    // softmax weight table (4 notes x 8 chunks) — accumulator-independent
    float W[NN_][NC_];
    #pragma unroll
    for (int c = 0; c < NC_; ++c) {
        int cnt = 0;
        #pragma unroll
        for (int i = 0; i < NN_; ++i) cnt += (ids[i] < c) ? 1 : 0;
        #pragma unroll
        for (int n = 0; n < NN_; ++n) {
            bool un = (ids[n] < c);
            W[n][c] = (cnt > 0) ? (un ? 1.0f / (float)cnt : 0.0f) : 0.25f;
        }
    }

    // ---- PDL gate: block until sum_kernel's REDGs are complete & visible ----
    // (no-op if PDL isn't active on this launch -> still correct, just serialized)
    asm volatile("griddepcontrol.wait;" ::: "memory");

    float CS[NC_], L[NC_];
    #pragma unroll
    for (int c = 0; c < NC_; ++c) {
        CS[c] = ldg_gpu(&g_CS[c * H_ + h]);
        L[c]  = ldg_gpu(&g_L [c * H_ + h]);
    }
    // Re-zero for the next replay: each thread clears exactly the slots it read.
    #pragma unroll
    for (int c = 0; c < NC_; ++c) {
        g_CS[c * H_ + h] = 0.f;
        g_L [c * H_ + h] = 0.f;
    }

    float Ptot = 0.f;
    #pragma unroll
    for (int c = 0; c < NC_; ++c) Ptot += CS[c];

    #pragma unroll
    for (int n = 0; n < NN_; ++n) {
        float dot = 0.f;
        #pragma unroll
        for (int c = 0; c < NC_; ++c) dot += W[n][c] * L[c];
        float score = Ptot * dot;

        // boundary corrections: j = 1115k straddles chunks (k-1, k) at prefix P[512k]
        float P = 0.f;
        #pragma unroll
        for (int k = 1; k < NC_; ++k) {
            P += CS[k - 1];
            float wd = W[n][k - 1] - W[n][k];
            score += wd * bnd[k - 1] * P;
        }
        out[n * H_ + h] = 1.0f / (1.0f + expf(-score));
    }
}

extern "C" void kernel_launch(void* const* d_in, const int* in_sizes, int n_in,
                              void* d_out, int out_size) {
    const float* enc = (const float*)d_in[0];   // encoding (4096, 768)
    // d_in[1] = label_queries: provably unused (softmax over the note axis cancels scores)
    const float* lw  = (const float*)d_in[2];   // label_weights flat (768*8921)
    const void*  ids = d_in[3];                 // note_end_chunk_ids (4, int32 or int64)
    float* out = (float*)d_out;                 // (4, 768) float32

    sum_kernel<<<GRID, 256>>>(enc, lw);

    // PDL launch: final2 may be scheduled while sum_kernel drains; it blocks at
    // griddepcontrol.wait until sum_kernel completes (implicit trigger).
    cudaLaunchConfig_t cfg = {};
    cfg.gridDim  = dim3(H_ / 128);
    cfg.blockDim = dim3(128);
    cfg.dynamicSmemBytes = 0;
    cfg.stream = 0;                              // same (legacy default) stream as <<<>>>
    cudaLaunchAttribute attr[1];
    attr[0].id = cudaLaunchAttributeProgrammaticStreamSerialization;
    attr[0].val.programmaticStreamSerializationAllowed = 1;
    cfg.attrs    = attr;
    cfg.numAttrs = 1;
    cudaError_t e = cudaLaunchKernelEx(&cfg, final2_kernel, lw, ids, (float*)out);
    if (e != cudaSuccess) {
        (void)cudaGetLastError();                // clear sticky error from rejected config
        // Fallback: plain serialized launch (correct either way)
        final2_kernel<<<H_ / 128, 128>>>(lw, ids, (float*)out);
    }
}

// round 16
// speedup vs baseline: 1.7582x; 1.1940x over previous
#include <cuda_runtime.h>
#include <math.h>

constexpr int H_   = 768;
constexpr int NC_  = 8;       // chunks
constexpr int NL_  = 8921;    // labels
constexpr int NN_  = 4;       // notes
constexpr int JB_  = 1115;    // lw bucket width (8921 = 8*1115 + 1)

constexpr int ESEG  = 16;     // segments per encoding chunk
constexpr int EROWS = 32;     // 16*32 = 512 rows/chunk
constexpr int LSEG  = 32;     // segments per lw bucket
constexpr int LROWS = 35;     // 32*35 = 1120 >= 1116
constexpr int HG    = 3;      // 768 / 256 column groups
constexpr int ENC_BLOCKS = NC_ * ESEG * HG;   // 384
constexpr int LW_BLOCKS  = NC_ * LSEG * HG;   // 768
constexpr int GRID       = ENC_BLOCKS + LW_BLOCKS;  // 1152

// Accumulators. Zero at module load; final2_kernel re-zeroes exactly the slots
// it consumed -> invariant "zero on entry to sum_kernel" holds on every graph
// replay. No counters, no gates, no fences.
__device__ float g_CS[NC_ * H_];          // per-chunk encoding column sums
__device__ float g_L [NC_ * H_];          // per-bucket lw column sums

__device__ __forceinline__ void redg_add(float* p, float v) {
    asm volatile("red.relaxed.gpu.global.add.f32 [%0], %1;" :: "l"(p), "f"(v) : "memory");
}
__device__ __forceinline__ float ldg_gpu(const float* p) {
    float v;
    asm volatile("ld.relaxed.gpu.global.f32 %0, [%1];" : "=f"(v) : "l"(p) : "memory");
    return v;
}

// ---------------- Kernel 1: streaming block sums; early PDL trigger ----------------
__global__ __launch_bounds__(256, 8) void sum_kernel(const float* __restrict__ enc,
                                                     const float* __restrict__ lw) {
    // Early trigger: once ALL primary blocks have executed this, the dependent
    // grid (final2) may be scheduled and run its prologue concurrently. Its
    // griddepcontrol.wait still blocks until this grid completes + flushes, so
    // the REDG results below are safely ordered.
    asm volatile("griddepcontrol.launch_dependents;" ::: "memory");

    const int b   = blockIdx.x;
    const int tid = threadIdx.x;

    if (b < ENC_BLOCKS) {
        int c   = b / (ESEG * HG);
        int rem = b % (ESEG * HG);
        int s   = rem / HG;
        int hg  = rem % HG;
        int h   = hg * 256 + tid;
        const float* p = enc + (size_t)(c * 512 + s * EROWS) * H_ + h;
        float a0 = 0.f, a1 = 0.f, a2 = 0.f, a3 = 0.f;
        #pragma unroll
        for (int r = 0; r < EROWS; r += 4) {
            a0 += p[(r + 0) * H_];
            a1 += p[(r + 1) * H_];
            a2 += p[(r + 2) * H_];
            a3 += p[(r + 3) * H_];
        }
        redg_add(&g_CS[c * H_ + h], (a0 + a1) + (a2 + a3));
    } else {
        int bb  = b - ENC_BLOCKS;
        int c   = bb / (LSEG * HG);
        int rem = bb % (LSEG * HG);
        int s   = rem / HG;
        int hg  = rem % HG;
        int h   = hg * 256 + tid;
        int r0   = c * JB_ + s * LROWS;
        int rend = min(r0 + LROWS, (c == NC_ - 1) ? NL_ : (c + 1) * JB_);
        float a0 = 0.f, a1 = 0.f, a2 = 0.f, a3 = 0.f;
        int r = r0;
        for (; r + 4 <= rend; r += 4) {
            a0 += lw[(size_t)(r + 0) * H_ + h];
            a1 += lw[(size_t)(r + 1) * H_ + h];
            a2 += lw[(size_t)(r + 2) * H_ + h];
            a3 += lw[(size_t)(r + 3) * H_ + h];
        }
        float tail = 0.f;
        for (; r < rend; ++r) tail += lw[(size_t)r * H_ + h];
        redg_add(&g_L[c * H_ + h], ((a0 + a1) + (a2 + a3)) + tail);
    }
}

// ---------------- Kernel 2 (PDL): prologue overlaps sum_kernel; wait; combine ----------------
__global__ __launch_bounds__(128) void final2_kernel(const float* __restrict__ lw,
                                                     const void* __restrict__ idsRaw,
                                                     float* __restrict__ out) {
    const int h = blockIdx.x * 128 + threadIdx.x;   // one column per thread, 768 total

    // ---- prologue: everything independent of the accumulators ----
    float bnd[NC_ - 1];
    #pragma unroll
    for (int k = 1; k < NC_; ++k)
        bnd[k - 1] = lw[(size_t)(JB_ * k) * H_ + h];

    // note_end_chunk_ids: detect int64 vs int32 layout
    const int* w = (const int*)idsRaw;
    int ids[NN_];
    {
        bool is64 = true;
        int v[NN_];
        #pragma unroll
        for (int i = 0; i < NN_; ++i) {
            int lo = w[2 * i], hi = w[2 * i + 1];
            v[i] = lo;
            if (hi != 0 || lo < 0 || lo >= NC_) is64 = false;
        }
        #pragma unroll
        for (int i = 0; i + 1 < NN_; ++i)
            if (v[i] > v[i + 1]) is64 = false;
        #pragma unroll
        for (int i = 0; i < NN_; ++i) ids[i] = is64 ? v[i] : w[i];
    }

    // softmax weight table (4 notes x 8 chunks) — accumulator-independent
    float W[NN_][NC_];
    #pragma unroll
    for (int c = 0; c < NC_; ++c) {
        int cnt = 0;
        #pragma unroll
        for (int i = 0; i < NN_; ++i) cnt += (ids[i] < c) ? 1 : 0;
        #pragma unroll
        for (int n = 0; n < NN_; ++n) {
            bool un = (ids[n] < c);
            W[n][c] = (cnt > 0) ? (un ? 1.0f / (float)cnt : 0.0f) : 0.25f;
        }
    }

    // ---- PDL gate: block until sum_kernel completes & its REDGs are visible ----
    // (no-op if PDL isn't active on this launch -> still correct, just serialized)
    asm volatile("griddepcontrol.wait;" ::: "memory");

    float CS[NC_], L[NC_];
    #pragma unroll
    for (int c = 0; c < NC_; ++c) {
        CS[c] = ldg_gpu(&g_CS[c * H_ + h]);
        L[c]  = ldg_gpu(&g_L [c * H_ + h]);
    }
    // Re-zero for the next replay: each thread clears exactly the slots it read.
    #pragma unroll
    for (int c = 0; c < NC_; ++c) {
        g_CS[c * H_ + h] = 0.f;
        g_L [c * H_ + h] = 0.f;
    }

    float Ptot = 0.f;
    #pragma unroll
    for (int c = 0; c < NC_; ++c) Ptot += CS[c];

    #pragma unroll
    for (int n = 0; n < NN_; ++n) {
        float dot = 0.f;
        #pragma unroll
        for (int c = 0; c < NC_; ++c) dot += W[n][c] * L[c];
        float score = Ptot * dot;

        // boundary corrections: j = 1115k straddles chunks (k-1, k) at prefix P[512k]
        float P = 0.f;
        #pragma unroll
        for (int k = 1; k < NC_; ++k) {
            P += CS[k - 1];
            float wd = W[n][k - 1] - W[n][k];
            score += wd * bnd[k - 1] * P;
        }
        out[n * H_ + h] = 1.0f / (1.0f + expf(-score));
    }
}

extern "C" void kernel_launch(void* const* d_in, const int* in_sizes, int n_in,
                              void* d_out, int out_size) {
    const float* enc = (const float*)d_in[0];   // encoding (4096, 768)
    // d_in[1] = label_queries: provably unused (softmax over the note axis cancels scores)
    const float* lw  = (const float*)d_in[2];   // label_weights flat (768*8921)
    const void*  ids = d_in[3];                 // note_end_chunk_ids (4, int32 or int64)
    float* out = (float*)d_out;                 // (4, 768) float32

    sum_kernel<<<GRID, 256>>>(enc, lw);

    // PDL launch: final2 becomes schedulable as soon as all sum_kernel blocks
    // execute launch_dependents; it parks at griddepcontrol.wait until
    // sum_kernel completes (memory flush included).
    cudaLaunchConfig_t cfg = {};
    cfg.gridDim  = dim3(H_ / 128);
    cfg.blockDim = dim3(128);
    cfg.dynamicSmemBytes = 0;
    cfg.stream = 0;                              // same (legacy default) stream as <<<>>>
    cudaLaunchAttribute attr[1];
    attr[0].id = cudaLaunchAttributeProgrammaticStreamSerialization;
    attr[0].val.programmaticStreamSerializationAllowed = 1;
    cfg.attrs    = attr;
    cfg.numAttrs = 1;
    cudaError_t e = cudaLaunchKernelEx(&cfg, final2_kernel, lw, ids, (float*)out);
    if (e != cudaSuccess) {
        (void)cudaGetLastError();                // clear sticky error from rejected config
        // Fallback: plain serialized launch (correct either way)
        final2_kernel<<<H_ / 128, 128>>>(lw, ids, (float*)out);
    }
}